// round 2
// baseline (speedup 1.0000x reference)
#include <cuda_runtime.h>
#include <math.h>

#define BB   4
#define NN   1024
#define CDIM 256
#define HH   4
#define DKK  64
#define GG   4
#define BH   (BB*HH)

// ---------------- scratch (device globals; no allocation) ----------------
// g_S is used for the raw cosine matrix AND (in place) the masked attention.
__device__ float g_S   [(size_t)BH * NN * NN];   // [bh][i][j]
__device__ float g_Nrm [(size_t)BH * NN];        // per-head norms [bh][i]
__device__ float g_vec [NN];                     // global top-k union mask
__device__ float g_pre [(size_t)BB * CDIM * NN]; // gconv output (stage1/2)
__device__ float g_out1[(size_t)BB * CDIM * NN]; // stage1 result (B,C,n)
__device__ float g_o1T [(size_t)BB * NN * CDIM]; // stage1 result (B,n,C)
__device__ float g_o2m [(size_t)BB * CDIM * NN]; // stage2 message

// ---------------- kernels ----------------

// per-head L2 norms. X is node-major (B*NN, CDIM). one warp per (b,i,h).
__global__ void norms_kernel(const float* __restrict__ X, float* __restrict__ Nrm) {
    int gw   = (blockIdx.x * blockDim.x + threadIdx.x) >> 5;
    int lane = threadIdx.x & 31;
    if (gw >= BB * NN * HH) return;
    int h  = gw & (HH - 1);
    int bi = gw >> 2;                 // b*NN + i
    const float* p = X + (size_t)bi * CDIM + h * DKK;
    float v0 = p[lane], v1 = p[lane + 32];
    float s = v0 * v0 + v1 * v1;
    #pragma unroll
    for (int off = 16; off; off >>= 1) s += __shfl_xor_sync(0xffffffffu, s, off);
    if (lane == 0) {
        int b = bi >> 10, i = bi & (NN - 1);
        Nrm[(size_t)(b * HH + h) * NN + i] = sqrtf(s);
    }
}

// S[bh,i,j] = relu( dot(x_i,x_j) / max(Ni*Nj, 1e-8) ).  64x64 tiles, K=64.
__global__ __launch_bounds__(256) void cos_gemm_kernel(
        const float* __restrict__ X, const float* __restrict__ Nrm,
        float* __restrict__ S) {
    int bh = blockIdx.z, b = bh >> 2, h = bh & 3;
    int it = blockIdx.y * 64, jt = blockIdx.x * 64;
    __shared__ float Ast[DKK][65];   // [k][m]
    __shared__ float Bst[DKK][65];   // [k][n]
    int tid = threadIdx.x;
    const float* Abase = X + ((size_t)(b * NN + it)) * CDIM + h * DKK;
    const float* Bbase = X + ((size_t)(b * NN + jt)) * CDIM + h * DKK;
    #pragma unroll
    for (int l = 0; l < 4; l++) {
        int idx = tid + l * 256;          // 0..1023
        int r = idx >> 4, c4 = idx & 15;
        float4 va = *(const float4*)(Abase + (size_t)r * CDIM + c4 * 4);
        float4 vb = *(const float4*)(Bbase + (size_t)r * CDIM + c4 * 4);
        Ast[c4*4+0][r] = va.x; Ast[c4*4+1][r] = va.y; Ast[c4*4+2][r] = va.z; Ast[c4*4+3][r] = va.w;
        Bst[c4*4+0][r] = vb.x; Bst[c4*4+1][r] = vb.y; Bst[c4*4+2][r] = vb.z; Bst[c4*4+3][r] = vb.w;
    }
    __syncthreads();
    int ty = tid >> 4, tx = tid & 15;
    float acc[4][4] = {};
    #pragma unroll 16
    for (int k = 0; k < DKK; k++) {
        float a[4], bv[4];
        #pragma unroll
        for (int u = 0; u < 4; u++) a[u]  = Ast[k][ty * 4 + u];
        #pragma unroll
        for (int v = 0; v < 4; v++) bv[v] = Bst[k][tx * 4 + v];
        #pragma unroll
        for (int u = 0; u < 4; u++)
            #pragma unroll
            for (int v = 0; v < 4; v++) acc[u][v] += a[u] * bv[v];
    }
    const float* Nb = Nrm + (size_t)bh * NN;
    float ni[4], nj[4];
    #pragma unroll
    for (int u = 0; u < 4; u++) ni[u] = Nb[it + ty * 4 + u];
    #pragma unroll
    for (int v = 0; v < 4; v++) nj[v] = Nb[jt + tx * 4 + v];
    float* Sout = S + (size_t)bh * NN * NN;
    #pragma unroll
    for (int u = 0; u < 4; u++)
        #pragma unroll
        for (int v = 0; v < 4; v++) {
            float d = fmaxf(ni[u] * nj[v], 1e-8f);
            float s = fmaxf(acc[u][v] / d, 0.0f);
            Sout[(size_t)(it + ty * 4 + u) * NN + jt + tx * 4 + v] = s;
        }
}

__global__ void zero_vec_kernel(float* __restrict__ vec) { vec[threadIdx.x] = 0.0f; }

// exact top-4 per (bh,i) row; union scatter into vec. one warp per row.
__global__ void topk_kernel(const float* __restrict__ S, float* __restrict__ vec) {
    int row  = blockIdx.x * (blockDim.x >> 5) + (threadIdx.x >> 5);
    int lane = threadIdx.x & 31;
    if (row >= BH * NN) return;
    const float* p = S + (size_t)row * NN;
    float v[4] = {-1e30f, -1e30f, -1e30f, -1e30f};
    int   id[4] = {0, 0, 0, 0};
    for (int j = lane; j < NN; j += 32) {
        float x = p[j];
        if (x > v[3]) {
            if (x > v[0])      { v[3]=v[2];id[3]=id[2]; v[2]=v[1];id[2]=id[1]; v[1]=v[0];id[1]=id[0]; v[0]=x; id[0]=j; }
            else if (x > v[1]) { v[3]=v[2];id[3]=id[2]; v[2]=v[1];id[2]=id[1]; v[1]=x; id[1]=j; }
            else if (x > v[2]) { v[3]=v[2];id[3]=id[2]; v[2]=x; id[2]=j; }
            else               { v[3]=x; id[3]=j; }
        }
    }
    #pragma unroll
    for (int r = 0; r < 4; r++) {
        float best = v[0]; int bl = lane;
        #pragma unroll
        for (int off = 16; off; off >>= 1) {
            float ov = __shfl_xor_sync(0xffffffffu, best, off);
            int   ol = __shfl_xor_sync(0xffffffffu, bl, off);
            if (ov > best || (ov == best && ol < bl)) { best = ov; bl = ol; }
        }
        int widx = __shfl_sync(0xffffffffu, id[0], bl);
        if (lane == 0) vec[widx] = 1.0f;
        if (lane == bl) { v[0]=v[1];id[0]=id[1]; v[1]=v[2];id[1]=id[2]; v[2]=v[3];id[2]=id[3]; v[3]=-1e30f; }
    }
}

// In place: A[bh,i,j] = (S*mroi[b,i,j]*sm[b,j]*vec[j] + (i==j)*fm_i) / 4
__global__ void maskapply_kernel(float* __restrict__ S,
                                 const int* __restrict__ mroi,
                                 const int* __restrict__ smask,
                                 const float* __restrict__ vec) {
    int bh = blockIdx.y, b = bh >> 2;
    int i  = blockIdx.x;
    size_t off = ((size_t)bh * NN + i) * NN;
    const int* mr  = mroi + ((size_t)b * NN + i) * NN;
    const int* smb = smask + (size_t)b * NN;
    float fm = (smb[i] == 0) ? 1.0f : 0.0f;
    for (int j = threadIdx.x; j < NN; j += blockDim.x) {
        float val = S[off + j] * (float)mr[j] * (float)smb[j] * vec[j];
        if (j == i) val += fm;
        S[off + j] = val * 0.25f;
    }
}

// grouped 1x1 conv + relu. Xin node-major (B,NN,CDIM); out (B,CDIM,NN).
__global__ __launch_bounds__(256) void gconv_kernel(
        const float* __restrict__ Xin, const float* __restrict__ W,
        const float* __restrict__ bias, float* __restrict__ out) {
    int b = blockIdx.z, g = blockIdx.y, nt = blockIdx.x * 64;
    __shared__ float Wst[64][65];    // [ci][o]
    __shared__ float Xst[64][65];    // [ci][n]
    int tid = threadIdx.x;
    const float* Wb = W + (size_t)g * 64 * 64;
    const float* Xb = Xin + ((size_t)b * NN + nt) * CDIM + g * 64;
    #pragma unroll
    for (int l = 0; l < 4; l++) {
        int idx = tid + l * 256; int r = idx >> 4, c4 = idx & 15;
        float4 w4 = *(const float4*)(Wb + (size_t)r * 64 + c4 * 4);
        Wst[c4*4+0][r] = w4.x; Wst[c4*4+1][r] = w4.y; Wst[c4*4+2][r] = w4.z; Wst[c4*4+3][r] = w4.w;
        float4 x4 = *(const float4*)(Xb + (size_t)r * CDIM + c4 * 4);
        Xst[c4*4+0][r] = x4.x; Xst[c4*4+1][r] = x4.y; Xst[c4*4+2][r] = x4.z; Xst[c4*4+3][r] = x4.w;
    }
    __syncthreads();
    int ty = tid >> 4, tx = tid & 15;
    float acc[4][4] = {};
    #pragma unroll 16
    for (int k = 0; k < 64; k++) {
        float a[4], bv[4];
        #pragma unroll
        for (int u = 0; u < 4; u++) a[u]  = Wst[k][ty * 4 + u];
        #pragma unroll
        for (int v = 0; v < 4; v++) bv[v] = Xst[k][tx * 4 + v];
        #pragma unroll
        for (int u = 0; u < 4; u++)
            #pragma unroll
            for (int v = 0; v < 4; v++) acc[u][v] += a[u] * bv[v];
    }
    #pragma unroll
    for (int u = 0; u < 4; u++) {
        int oc = g * 64 + ty * 4 + u;
        float bs = bias[oc];
        #pragma unroll
        for (int v = 0; v < 4; v++) {
            float val = fmaxf(acc[u][v] + bs, 0.0f);
            out[((size_t)b * CDIM + oc) * NN + nt + tx * 4 + v] = val;
        }
    }
}

// o[b,h*64+cc,i] = sum_j U[b,h*64+cc,j] * A[bh,i,j]  (+ pre if given)
__global__ __launch_bounds__(256) void ogemm_kernel(
        const float* __restrict__ U, const float* __restrict__ Am,
        const float* __restrict__ pre, float* __restrict__ out) {
    int bh = blockIdx.y, b = bh >> 2, h = bh & 3;
    int it = blockIdx.x * 64;
    __shared__ float Ust[64][65];    // [k][cc]
    __shared__ float Ast[64][65];    // [k][i]
    const float* Ub = U  + ((size_t)b * CDIM + h * 64) * NN;
    const float* Ab = Am + ((size_t)bh * NN + it) * NN;
    int tid = threadIdx.x, ty = tid >> 4, tx = tid & 15;
    float acc[4][4] = {};
    for (int k0 = 0; k0 < NN; k0 += 64) {
        #pragma unroll
        for (int l = 0; l < 4; l++) {
            int idx = tid + l * 256; int r = idx >> 4, c4 = idx & 15;
            float4 u4 = *(const float4*)(Ub + (size_t)r * NN + k0 + c4 * 4);
            Ust[c4*4+0][r] = u4.x; Ust[c4*4+1][r] = u4.y; Ust[c4*4+2][r] = u4.z; Ust[c4*4+3][r] = u4.w;
            float4 a4 = *(const float4*)(Ab + (size_t)r * NN + k0 + c4 * 4);
            Ast[c4*4+0][r] = a4.x; Ast[c4*4+1][r] = a4.y; Ast[c4*4+2][r] = a4.z; Ast[c4*4+3][r] = a4.w;
        }
        __syncthreads();
        #pragma unroll 16
        for (int k = 0; k < 64; k++) {
            float a[4], bv[4];
            #pragma unroll
            for (int u = 0; u < 4; u++) a[u]  = Ust[k][ty * 4 + u];
            #pragma unroll
            for (int v = 0; v < 4; v++) bv[v] = Ast[k][tx * 4 + v];
            #pragma unroll
            for (int u = 0; u < 4; u++)
                #pragma unroll
                for (int v = 0; v < 4; v++) acc[u][v] += a[u] * bv[v];
        }
        __syncthreads();
    }
    #pragma unroll
    for (int u = 0; u < 4; u++) {
        int oc = h * 64 + ty * 4 + u;
        #pragma unroll
        for (int v = 0; v < 4; v++) {
            size_t o = ((size_t)b * CDIM + oc) * NN + it + tx * 4 + v;
            float val = acc[u][v];
            if (pre != nullptr) val += pre[o];
            out[o] = val;
        }
    }
}

// (B,CDIM,NN) -> (B,NN,CDIM)
__global__ void transpose_kernel(const float* __restrict__ in, float* __restrict__ out) {
    __shared__ float t[32][33];
    int b = blockIdx.z;
    int c0 = blockIdx.y * 32, n0 = blockIdx.x * 32;
    int x = threadIdx.x, y = threadIdx.y;
    for (int yy = y; yy < 32; yy += 8)
        t[yy][x] = in[((size_t)b * CDIM + c0 + yy) * NN + n0 + x];
    __syncthreads();
    for (int yy = y; yy < 32; yy += 8)
        out[((size_t)b * NN + n0 + yy) * CDIM + c0 + x] = t[x][yy];
}

// gts[m,o] = relu(sum_c F[m,c]*W[o,c] + b[o]),  m = b*NN+n
__global__ __launch_bounds__(256) void gts_kernel(
        const float* __restrict__ F, const float* __restrict__ W,
        const float* __restrict__ bias, float* __restrict__ out) {
    int mt = blockIdx.y * 64, ntc = blockIdx.x * 64;
    __shared__ float Fst[64][65];
    __shared__ float Wst[64][65];
    int tid = threadIdx.x, ty = tid >> 4, tx = tid & 15;
    float acc[4][4] = {};
    for (int k0 = 0; k0 < CDIM; k0 += 64) {
        #pragma unroll
        for (int l = 0; l < 4; l++) {
            int idx = tid + l * 256; int r = idx >> 4, c4 = idx & 15;
            float4 f4 = *(const float4*)(F + (size_t)(mt + r) * CDIM + k0 + c4 * 4);
            Fst[c4*4+0][r] = f4.x; Fst[c4*4+1][r] = f4.y; Fst[c4*4+2][r] = f4.z; Fst[c4*4+3][r] = f4.w;
            float4 w4 = *(const float4*)(W + (size_t)(ntc + r) * CDIM + k0 + c4 * 4);
            Wst[c4*4+0][r] = w4.x; Wst[c4*4+1][r] = w4.y; Wst[c4*4+2][r] = w4.z; Wst[c4*4+3][r] = w4.w;
        }
        __syncthreads();
        #pragma unroll 16
        for (int k = 0; k < 64; k++) {
            float a[4], bv[4];
            #pragma unroll
            for (int u = 0; u < 4; u++) a[u]  = Fst[k][ty * 4 + u];
            #pragma unroll
            for (int v = 0; v < 4; v++) bv[v] = Wst[k][tx * 4 + v];
            #pragma unroll
            for (int u = 0; u < 4; u++)
                #pragma unroll
                for (int v = 0; v < 4; v++) acc[u][v] += a[u] * bv[v];
        }
        __syncthreads();
    }
    #pragma unroll
    for (int u = 0; u < 4; u++)
        #pragma unroll
        for (int v = 0; v < 4; v++) {
            int oc = ntc + tx * 4 + v;
            float val = fmaxf(acc[u][v] + bias[oc], 0.0f);
            out[(size_t)(mt + ty * 4 + u) * CDIM + oc] = val;
        }
}

// LayerNorm over channels of y[b,n,c] = o2m[b,c,n]; writes node_feat and out0.
__global__ void final_kernel(const float* __restrict__ o2m,
                             const float* __restrict__ out2pre,
                             const float* __restrict__ lnw, const float* __restrict__ lnb,
                             float* __restrict__ out0, float* __restrict__ outnf) {
    int b = blockIdx.y, n = blockIdx.x;
    int c = threadIdx.x;
    float y = o2m[((size_t)b * CDIM + c) * NN + n];
    __shared__ float s1[256], s2[256];
    s1[c] = y; s2[c] = y * y;
    __syncthreads();
    for (int st = 128; st; st >>= 1) {
        if (c < st) { s1[c] += s1[c + st]; s2[c] += s2[c + st]; }
        __syncthreads();
    }
    float mu  = s1[0] * (1.0f / CDIM);
    float var = s2[0] * (1.0f / CDIM) - mu * mu;
    float rstd = rsqrtf(fmaxf(var, 0.0f) + 1e-6f);
    float nf = (y - mu) * rstd * lnw[c] + lnb[c];
    size_t oidx = ((size_t)b * NN + n) * CDIM + c;
    outnf[oidx] = nf;
    out0[oidx]  = out2pre[((size_t)b * CDIM + c) * NN + n] + nf;
}

// ---------------- launcher ----------------
extern "C" void kernel_launch(void* const* d_in, const int* in_sizes, int n_in,
                              void* d_out, int out_size) {
    (void)in_sizes; (void)n_in; (void)out_size;
    const float* input   = (const float*)d_in[0];
    const int*   mroi    = (const int*)  d_in[1];
    const int*   smask   = (const int*)  d_in[2];
    const float* gt_feat = (const float*)d_in[3];
    const float* w1      = (const float*)d_in[4];
    const float* b1      = (const float*)d_in[5];
    const float* w2      = (const float*)d_in[6];
    const float* b2      = (const float*)d_in[7];
    const float* gt_w    = (const float*)d_in[8];
    const float* gt_b    = (const float*)d_in[9];
    const float* lnw     = (const float*)d_in[10];
    const float* lnb     = (const float*)d_in[11];

    float* out0    = (float*)d_out;                           // out2.T (B,NN,C)
    float* out_gts = out0 + (size_t)BB * NN * CDIM;           // gts
    float* out_nf  = out0 + 2 * (size_t)BB * NN * CDIM;       // node_feat

    float *S, *Nrm, *vec, *pre, *out1, *o1T, *o2m;
    cudaGetSymbolAddress((void**)&S,    g_S);
    cudaGetSymbolAddress((void**)&Nrm,  g_Nrm);
    cudaGetSymbolAddress((void**)&vec,  g_vec);
    cudaGetSymbolAddress((void**)&pre,  g_pre);
    cudaGetSymbolAddress((void**)&out1, g_out1);
    cudaGetSymbolAddress((void**)&o1T,  g_o1T);
    cudaGetSymbolAddress((void**)&o2m,  g_o2m);

    // independent gts branch
    gts_kernel<<<dim3(CDIM / 64, (BB * NN) / 64), 256>>>(gt_feat, gt_w, gt_b, out_gts);

    // ---- stage 1 ----
    norms_kernel<<<(BB * NN * HH) / 8, 256>>>(input, Nrm);
    cos_gemm_kernel<<<dim3(NN / 64, NN / 64, BH), 256>>>(input, Nrm, S);
    zero_vec_kernel<<<1, NN>>>(vec);
    topk_kernel<<<(BH * NN) / 8, 256>>>(S, vec);
    maskapply_kernel<<<dim3(NN, BH), 256>>>(S, mroi, smask, vec);
    gconv_kernel<<<dim3(NN / 64, GG, BB), 256>>>(input, w1, b1, pre);
    ogemm_kernel<<<dim3(NN / 64, BH), 256>>>(pre, S, pre, out1);   // out1 = pre + msg
    transpose_kernel<<<dim3(NN / 32, CDIM / 32, BB), dim3(32, 8)>>>(out1, o1T);

    // ---- stage 2 ----
    norms_kernel<<<(BB * NN * HH) / 8, 256>>>(o1T, Nrm);
    cos_gemm_kernel<<<dim3(NN / 64, NN / 64, BH), 256>>>(o1T, Nrm, S);
    zero_vec_kernel<<<1, NN>>>(vec);
    topk_kernel<<<(BH * NN) / 8, 256>>>(S, vec);
    maskapply_kernel<<<dim3(NN, BH), 256>>>(S, mroi, smask, vec);
    gconv_kernel<<<dim3(NN / 64, GG, BB), 256>>>(o1T, w2, b2, pre);      // out2_pre
    ogemm_kernel<<<dim3(NN / 64, BH), 256>>>(pre, S, nullptr, o2m);      // o2m only
    final_kernel<<<dim3(NN, BB), 256>>>(o2m, pre, lnw, lnb, out0, out_nf);
}